// round 1
// baseline (speedup 1.0000x reference)
#include <cuda_runtime.h>

// Problem constants (fixed by the dataset): B=8, N=E=2048.
#define BATCH 8
#define NN 2048
#define EE 2048

// SGEMM tiling
#define BM 128
#define BN 128
#define BK 16
#define TM 8
#define TN 8

// Scratch: device globals (no cudaMalloc allowed).
__device__ __align__(256) float g_q[(size_t)BATCH * NN * EE];   // Q = X W^T + b   [B, N, E]
__device__ __align__(256) float g_s[(size_t)BATCH * NN * NN];   // scores -> attn  [B, N, N]
__device__ __align__(256) float g_cmax[BATCH * NN];
__device__ __align__(256) float g_csum[BATCH * NN];             // stores 1/sum

// C[m,n] = sum_k A[m,k] * B[n,k] (+ bias[n])   — NT GEMM, row-major everything.
// Batched via blockIdx.z with element strides sA/sB/sC.
__global__ __launch_bounds__(256, 2)
void sgemm_nt(const float* __restrict__ Ag, const float* __restrict__ Bg,
              float* __restrict__ Cg, const float* __restrict__ bias,
              int M, int N, int K,
              long long sA, long long sB, long long sC)
{
    const float* A = Ag + (size_t)blockIdx.z * (size_t)sA;
    const float* B = Bg + (size_t)blockIdx.z * (size_t)sB;
    float*       C = Cg + (size_t)blockIdx.z * (size_t)sC;

    __shared__ float As[BK][BM];
    __shared__ float Bs[BK][BN];

    const int tid  = threadIdx.x;
    const int row0 = blockIdx.y * BM;
    const int col0 = blockIdx.x * BN;

    const int tr = tid >> 4;          // 0..15 : thread row in 16x16 grid
    const int tc = tid & 15;          // 0..15 : thread col

    // Global-load mapping: each thread fetches 2 float4 from A and 2 from B per tile.
    const int lr = tid >> 2;          // 0..63
    const int lc = (tid & 3) << 2;    // 0,4,8,12

    const float* Aload = A + (size_t)(row0 + lr) * K + lc;
    const float* Bload = B + (size_t)(col0 + lr) * K + lc;

    float acc[TM][TN];
#pragma unroll
    for (int i = 0; i < TM; i++)
#pragma unroll
        for (int j = 0; j < TN; j++)
            acc[i][j] = 0.0f;

    // Prologue: stage tile k0=0 in registers.
    float4 a0 = *(const float4*)(Aload);
    float4 a1 = *(const float4*)(Aload + (size_t)64 * K);
    float4 b0 = *(const float4*)(Bload);
    float4 b1 = *(const float4*)(Bload + (size_t)64 * K);

    for (int k0 = 0; k0 < K; k0 += BK) {
        __syncthreads();  // previous tile's smem reads complete
        As[lc + 0][lr]      = a0.x; As[lc + 1][lr]      = a0.y;
        As[lc + 2][lr]      = a0.z; As[lc + 3][lr]      = a0.w;
        As[lc + 0][lr + 64] = a1.x; As[lc + 1][lr + 64] = a1.y;
        As[lc + 2][lr + 64] = a1.z; As[lc + 3][lr + 64] = a1.w;
        Bs[lc + 0][lr]      = b0.x; Bs[lc + 1][lr]      = b0.y;
        Bs[lc + 2][lr]      = b0.z; Bs[lc + 3][lr]      = b0.w;
        Bs[lc + 0][lr + 64] = b1.x; Bs[lc + 1][lr + 64] = b1.y;
        Bs[lc + 2][lr + 64] = b1.z; Bs[lc + 3][lr + 64] = b1.w;
        __syncthreads();

        // Prefetch next tile into registers (overlaps with compute below).
        if (k0 + BK < K) {
            a0 = *(const float4*)(Aload + k0 + BK);
            a1 = *(const float4*)(Aload + (size_t)64 * K + k0 + BK);
            b0 = *(const float4*)(Bload + k0 + BK);
            b1 = *(const float4*)(Bload + (size_t)64 * K + k0 + BK);
        }

#pragma unroll
        for (int kk = 0; kk < BK; kk++) {
            float ar[TM], br[TN];
            *(float4*)&ar[0] = *(const float4*)&As[kk][tr * 8];
            *(float4*)&ar[4] = *(const float4*)&As[kk][tr * 8 + 4];
            *(float4*)&br[0] = *(const float4*)&Bs[kk][tc * 8];
            *(float4*)&br[4] = *(const float4*)&Bs[kk][tc * 8 + 4];
#pragma unroll
            for (int i = 0; i < TM; i++)
#pragma unroll
                for (int j = 0; j < TN; j++)
                    acc[i][j] = fmaf(ar[i], br[j], acc[i][j]);
        }
    }

#pragma unroll
    for (int i = 0; i < TM; i++) {
        const int r = row0 + tr * 8 + i;
#pragma unroll
        for (int j = 0; j < TN; j += 4) {
            const int c = col0 + tc * 8 + j;
            float4 v = make_float4(acc[i][j], acc[i][j + 1], acc[i][j + 2], acc[i][j + 3]);
            if (bias) {
                v.x += __ldg(bias + c);
                v.y += __ldg(bias + c + 1);
                v.z += __ldg(bias + c + 2);
                v.w += __ldg(bias + c + 3);
            }
            *(float4*)(C + (size_t)r * N + c) = v;
        }
    }
}

// Column-wise (axis=1) online softmax statistics: for each batch b and column j,
// reduce over rows i. Threads -> columns (coalesced), loop -> rows.
__global__ void col_stats(const float* __restrict__ S,
                          float* __restrict__ cmax, float* __restrict__ crsum)
{
    const int b = blockIdx.y;
    const int j = blockIdx.x * blockDim.x + threadIdx.x;
    const float* Sb = S + (size_t)b * NN * NN + j;

    float m[4] = {-1e30f, -1e30f, -1e30f, -1e30f};
    float s[4] = {0.f, 0.f, 0.f, 0.f};
    for (int i = 0; i < NN; i += 4) {
#pragma unroll
        for (int u = 0; u < 4; u++) {
            float v  = Sb[(size_t)(i + u) * NN];
            float nm = fmaxf(m[u], v);
            s[u] = s[u] * __expf(m[u] - nm) + __expf(v - nm);
            m[u] = nm;
        }
    }
    float M = fmaxf(fmaxf(m[0], m[1]), fmaxf(m[2], m[3]));
    float T = s[0] * __expf(m[0] - M) + s[1] * __expf(m[1] - M)
            + s[2] * __expf(m[2] - M) + s[3] * __expf(m[3] - M);
    cmax[b * NN + j]  = M;
    crsum[b * NN + j] = 1.0f / T;
}

// attn[i,j] = exp(S[i,j] - cmax[j]) * crsum[j], in place. float4 vectorized.
__global__ void col_norm(float* __restrict__ S,
                         const float* __restrict__ cmax, const float* __restrict__ crsum)
{
    const int b    = blockIdx.y;
    const int lin  = blockIdx.x * blockDim.x + threadIdx.x;   // quad index in [0, NN*NN/4)
    const int i    = lin >> 9;                                 // / (NN/4)
    const int j4   = (lin & 511) << 2;
    float* p = S + (size_t)b * NN * NN + (size_t)i * NN + j4;

    float4 v  = *(float4*)p;
    float4 mx = *(const float4*)(cmax  + b * NN + j4);
    float4 rs = *(const float4*)(crsum + b * NN + j4);
    v.x = __expf(v.x - mx.x) * rs.x;
    v.y = __expf(v.y - mx.y) * rs.y;
    v.z = __expf(v.z - mx.z) * rs.z;
    v.w = __expf(v.w - mx.w) * rs.w;
    *(float4*)p = v;
}

extern "C" void kernel_launch(void* const* d_in, const int* in_sizes, int n_in,
                              void* d_out, int out_size)
{
    const float* X    = (const float*)d_in[0];   // [B, N, E]
    const float* W    = (const float*)d_in[1];   // [E, E]
    const float* bvec = (const float*)d_in[2];   // [E]
    // d_in[3] = gamma: softmax is shift-invariant, gamma cancels — unused.
    float* out = (float*)d_out;                  // [B, N, N]

    float *q, *s, *cmax, *csum;
    cudaGetSymbolAddress((void**)&q,    g_q);
    cudaGetSymbolAddress((void**)&s,    g_s);
    cudaGetSymbolAddress((void**)&cmax, g_cmax);
    cudaGetSymbolAddress((void**)&csum, g_csum);

    const dim3 blk(256);

    // GEMM1: Q[B*N, E] = X[B*N, E] @ W[E, E]^T + b
    {
        dim3 grid(EE / BN, (BATCH * NN) / BM, 1);
        sgemm_nt<<<grid, blk>>>(X, W, q, bvec, BATCH * NN, EE, EE, 0, 0, 0);
    }
    // GEMM2: S[b] = Q[b] @ X[b]^T   (gamma dropped: shift-invariant under softmax)
    {
        dim3 grid(NN / BN, NN / BM, BATCH);
        sgemm_nt<<<grid, blk>>>(q, X, s, nullptr, NN, NN, EE,
                                (long long)NN * EE, (long long)NN * EE,
                                (long long)NN * NN);
    }
    // Softmax over axis=1 (columns of S), in place.
    {
        dim3 grid(NN / 256, BATCH);
        col_stats<<<grid, 256>>>(s, cmax, csum);
    }
    {
        dim3 grid((NN * NN / 4) / 256, BATCH);
        col_norm<<<grid, 256>>>(s, cmax, csum);
    }
    // GEMM3: O[b] = X[b] @ Attn[b]^T
    {
        dim3 grid(NN / BN, NN / BM, BATCH);
        sgemm_nt<<<grid, blk>>>(X, s, out, nullptr, NN, NN, EE,
                                (long long)NN * EE, (long long)NN * NN,
                                (long long)NN * NN);
    }
}

// round 3
// speedup vs baseline: 2.4745x; 2.4745x over previous
#include <cuda_runtime.h>
#include <cuda_bf16.h>
#include <cstdint>

#define BATCH 8
#define NN 2048
#define EE 2048

#define BM 128
#define BN 128
#define BK 64
#define STAGES 3
#define STAGE_BYTES 32768       // A: 128x128B (16KB) + B: 128x128B (16KB)
#define NBK 96                  // 3 phases x 32 k-blocks of 64

// ---------------- scratch globals (no cudaMalloc allowed) ----------------
__device__ __align__(256) __nv_bfloat16 g_xh[(size_t)BATCH * NN * EE];
__device__ __align__(256) __nv_bfloat16 g_xl[(size_t)BATCH * NN * EE];
__device__ __align__(256) __nv_bfloat16 g_wh[(size_t)EE * EE];
__device__ __align__(256) __nv_bfloat16 g_wl[(size_t)EE * EE];
__device__ __align__(256) __nv_bfloat16 g_qh[(size_t)BATCH * NN * EE];
__device__ __align__(256) __nv_bfloat16 g_ql[(size_t)BATCH * NN * EE];
__device__ __align__(256) __nv_bfloat16 g_ah[(size_t)BATCH * NN * NN];
__device__ __align__(256) __nv_bfloat16 g_al[(size_t)BATCH * NN * NN];
__device__ __align__(256) float         g_s [(size_t)BATCH * NN * NN];
__device__ __align__(256) float         g_cmax[BATCH * NN];
__device__ __align__(256) float         g_csum[BATCH * NN];

// ---------------- helpers ----------------
__device__ __forceinline__ uint32_t smem_u32(const void* p) {
    uint32_t a;
    asm("{ .reg .u64 t; cvta.to.shared.u64 t, %1; cvt.u32.u64 %0, t; }" : "=r"(a) : "l"(p));
    return a;
}
__device__ __forceinline__ void cp16(uint32_t s, const void* g) {
    asm volatile("cp.async.cg.shared.global [%0], [%1], 16;" :: "r"(s), "l"(g) : "memory");
}
__device__ __forceinline__ void cp_commit() {
    asm volatile("cp.async.commit_group;" ::: "memory");
}
template <int N> __device__ __forceinline__ void cp_wait() {
    asm volatile("cp.async.wait_group %0;" :: "n"(N) : "memory");
}
__device__ __forceinline__ void ldm4(uint32_t* r, uint32_t a) {
    asm volatile("ldmatrix.sync.aligned.m8n8.x4.shared.b16 {%0,%1,%2,%3}, [%4];"
                 : "=r"(r[0]), "=r"(r[1]), "=r"(r[2]), "=r"(r[3]) : "r"(a));
}
__device__ __forceinline__ void mma16816(float* c, const uint32_t* a, uint32_t b0, uint32_t b1) {
    asm volatile(
        "mma.sync.aligned.m16n8k16.row.col.f32.bf16.bf16.f32 "
        "{%0,%1,%2,%3}, {%4,%5,%6,%7}, {%8,%9}, {%0,%1,%2,%3};"
        : "+f"(c[0]), "+f"(c[1]), "+f"(c[2]), "+f"(c[3])
        : "r"(a[0]), "r"(a[1]), "r"(a[2]), "r"(a[3]), "r"(b0), "r"(b1));
}

// ---------------- tensor-core GEMM: C[128x128 tile] = A @ B^T, 3-phase bf16 split ----
// Phases: A (p0,p1,p2) x B (p0,p1,p2); all matrices [rows, 2048] bf16, k-contiguous.
// mode 0: write fp32 to outF. mode 1: add bias, split-store hi/lo bf16 to outH/outL.
__global__ __launch_bounds__(256, 1)
void gemm_mma(const __nv_bfloat16* pA0, const __nv_bfloat16* pA1, const __nv_bfloat16* pA2,
              const __nv_bfloat16* pB0, const __nv_bfloat16* pB1, const __nv_bfloat16* pB2,
              long long aBatch, long long bBatch, long long cBatch,
              float* outF, __nv_bfloat16* outH, __nv_bfloat16* outL,
              const float* __restrict__ bias, int mode)
{
    extern __shared__ __align__(128) char smem[];
    const uint32_t stg0 = smem_u32(smem);
    const int tid  = threadIdx.x;
    const int lane = tid & 31;
    const int warp = tid >> 5;
    const int row0 = blockIdx.y * BM;
    const int col0 = blockIdx.x * BN;
    const int z    = blockIdx.z;

    // -------- global->smem producer mapping (all 256 threads) --------
    const int lr = tid >> 3;        // 0..31 row group
    const int lc = tid & 7;         // 16B chunk within 128B row
    const uint32_t so = (uint32_t)(lr * 128 + ((lc ^ (lr & 7)) << 4));

    const __nv_bfloat16* pA[3] = {pA0, pA1, pA2};
    const __nv_bfloat16* pB[3] = {pB0, pB1, pB2};
    const char* gA[3]; const char* gB[3];
#pragma unroll
    for (int p = 0; p < 3; p++) {
        gA[p] = (const char*)(pA[p] + (size_t)z * (size_t)aBatch + (size_t)(row0 + lr) * EE) + lc * 16;
        gB[p] = (const char*)(pB[p] + (size_t)z * (size_t)bBatch + (size_t)(col0 + lr) * EE) + lc * 16;
    }

    // -------- mma fragment addressing precompute --------
    const int wm  = warp & 3;            // 4 warps down M
    const int wn  = warp >> 2;           // 2 warps across N
    const int m0w = wm * 32;
    const int n0w = wn * 64;
    const uint32_t aRow  = (uint32_t)(m0w + (lane & 15));
    const uint32_t aBase = aRow * 128;
    const uint32_t aXor  = aRow & 7;
    const uint32_t ac0   = (uint32_t)(lane >> 4);
    const uint32_t bRow  = (uint32_t)(n0w + ((lane >> 4) << 3) + (lane & 7));
    const uint32_t bBase = 16384u + bRow * 128;
    const uint32_t bXor  = (uint32_t)(lane & 7);
    const uint32_t bc0   = (uint32_t)((lane >> 3) & 1);

    float acc[2][8][4] = {};

    // -------- pipeline --------
    auto load_stage = [&](int s, int kb) {
        const int p = kb >> 5;
        const uint32_t koff = (uint32_t)(kb & 31) * 128;
        const uint32_t dstA = stg0 + (uint32_t)s * STAGE_BYTES + so;
        const uint32_t dstB = dstA + 16384u;
        const char* a = gA[p] + koff;
        const char* b = gB[p] + koff;
#pragma unroll
        for (int i = 0; i < 4; i++) {
            cp16(dstA + i * 4096u, a + (size_t)i * 131072);   // 32 rows * 4096B
            cp16(dstB + i * 4096u, b + (size_t)i * 131072);
        }
        cp_commit();
    };

    load_stage(0, 0);
    load_stage(1, 1);

    for (int kb = 0; kb < NBK; kb++) {
        if (kb + 1 < NBK) cp_wait<1>(); else cp_wait<0>();
        __syncthreads();
        if (kb + 2 < NBK) load_stage((kb + 2) % 3, kb + 2);

        const uint32_t sb = stg0 + (uint32_t)(kb % 3) * STAGE_BYTES;
#pragma unroll
        for (int ks = 0; ks < 4; ks++) {
            uint32_t af[2][4], bf[4][4];
#pragma unroll
            for (int mt = 0; mt < 2; mt++)
                ldm4(af[mt], sb + aBase + mt * 2048u + ((((uint32_t)ks * 2 + ac0) ^ aXor) << 4));
#pragma unroll
            for (int np = 0; np < 4; np++)
                ldm4(bf[np], sb + bBase + np * 2048u + ((((uint32_t)ks * 2 + bc0) ^ bXor) << 4));
#pragma unroll
            for (int mt = 0; mt < 2; mt++)
#pragma unroll
                for (int np = 0; np < 4; np++) {
                    mma16816(acc[mt][np * 2],     af[mt], bf[np][0], bf[np][1]);
                    mma16816(acc[mt][np * 2 + 1], af[mt], bf[np][2], bf[np][3]);
                }
        }
    }

    // -------- epilogue --------
    const int g  = lane >> 2;
    const int tg = lane & 3;
    if (mode == 0) {
        float* base = outF + (size_t)z * (size_t)cBatch;
#pragma unroll
        for (int mt = 0; mt < 2; mt++) {
            const int rg = row0 + m0w + mt * 16 + g;
#pragma unroll
            for (int nt = 0; nt < 8; nt++) {
                const int cg = col0 + n0w + nt * 8 + 2 * tg;
                float2 v01 = make_float2(acc[mt][nt][0], acc[mt][nt][1]);
                float2 v23 = make_float2(acc[mt][nt][2], acc[mt][nt][3]);
                *(float2*)(base + (size_t)rg * 2048 + cg)       = v01;
                *(float2*)(base + (size_t)(rg + 8) * 2048 + cg) = v23;
            }
        }
    } else {
#pragma unroll
        for (int mt = 0; mt < 2; mt++) {
            const int rg = row0 + m0w + mt * 16 + g;
#pragma unroll
            for (int nt = 0; nt < 8; nt++) {
                const int cg = col0 + n0w + nt * 8 + 2 * tg;
                const float b0 = __ldg(bias + cg), b1 = __ldg(bias + cg + 1);
                float v[4] = {acc[mt][nt][0] + b0, acc[mt][nt][1] + b1,
                              acc[mt][nt][2] + b0, acc[mt][nt][3] + b1};
                __nv_bfloat16 h0 = __float2bfloat16(v[0]), h1 = __float2bfloat16(v[1]);
                __nv_bfloat16 h2 = __float2bfloat16(v[2]), h3 = __float2bfloat16(v[3]);
                __nv_bfloat16 l0 = __float2bfloat16(v[0] - __bfloat162float(h0));
                __nv_bfloat16 l1 = __float2bfloat16(v[1] - __bfloat162float(h1));
                __nv_bfloat16 l2 = __float2bfloat16(v[2] - __bfloat162float(h2));
                __nv_bfloat16 l3 = __float2bfloat16(v[3] - __bfloat162float(h3));
                *(__nv_bfloat162*)(outH + (size_t)rg * 2048 + cg)       = __nv_bfloat162(h0, h1);
                *(__nv_bfloat162*)(outL + (size_t)rg * 2048 + cg)       = __nv_bfloat162(l0, l1);
                *(__nv_bfloat162*)(outH + (size_t)(rg + 8) * 2048 + cg) = __nv_bfloat162(h2, h3);
                *(__nv_bfloat162*)(outL + (size_t)(rg + 8) * 2048 + cg) = __nv_bfloat162(l2, l3);
            }
        }
    }
}

// ---------------- fp32 -> (bf16 hi, bf16 lo) split ----------------
__global__ void split_hl(const float* __restrict__ src,
                         __nv_bfloat16* __restrict__ h, __nv_bfloat16* __restrict__ l)
{
    const size_t i = ((size_t)blockIdx.x * blockDim.x + threadIdx.x) * 4;
    float4 v = *(const float4*)(src + i);
    __nv_bfloat16 h0 = __float2bfloat16(v.x), h1 = __float2bfloat16(v.y);
    __nv_bfloat16 h2 = __float2bfloat16(v.z), h3 = __float2bfloat16(v.w);
    *(__nv_bfloat162*)(h + i)     = __nv_bfloat162(h0, h1);
    *(__nv_bfloat162*)(h + i + 2) = __nv_bfloat162(h2, h3);
    *(__nv_bfloat162*)(l + i)     = __nv_bfloat162(__float2bfloat16(v.x - __bfloat162float(h0)),
                                                   __float2bfloat16(v.y - __bfloat162float(h1)));
    *(__nv_bfloat162*)(l + i + 2) = __nv_bfloat162(__float2bfloat16(v.z - __bfloat162float(h2)),
                                                   __float2bfloat16(v.w - __bfloat162float(h3)));
}

// ---------------- column softmax (axis=1) ----------------
__global__ void col_stats(const float* __restrict__ S,
                          float* __restrict__ cmax, float* __restrict__ crsum)
{
    const int b = blockIdx.y;
    const int j = blockIdx.x * blockDim.x + threadIdx.x;
    const float* Sb = S + (size_t)b * NN * NN + j;
    float m[4] = {-1e30f, -1e30f, -1e30f, -1e30f};
    float s[4] = {0.f, 0.f, 0.f, 0.f};
    for (int i = 0; i < NN; i += 4) {
#pragma unroll
        for (int u = 0; u < 4; u++) {
            float v  = Sb[(size_t)(i + u) * NN];
            float nm = fmaxf(m[u], v);
            s[u] = s[u] * __expf(m[u] - nm) + __expf(v - nm);
            m[u] = nm;
        }
    }
    float M = fmaxf(fmaxf(m[0], m[1]), fmaxf(m[2], m[3]));
    float T = s[0] * __expf(m[0] - M) + s[1] * __expf(m[1] - M)
            + s[2] * __expf(m[2] - M) + s[3] * __expf(m[3] - M);
    cmax[b * NN + j]  = M;
    crsum[b * NN + j] = 1.0f / T;
}

__global__ void col_norm_split(const float* __restrict__ S,
                               const float* __restrict__ cmax, const float* __restrict__ crsum,
                               __nv_bfloat16* __restrict__ ah, __nv_bfloat16* __restrict__ al)
{
    const int b   = blockIdx.y;
    const int lin = blockIdx.x * blockDim.x + threadIdx.x;
    const int i   = lin >> 9;
    const int j4  = (lin & 511) << 2;
    const size_t off = (size_t)b * NN * NN + (size_t)i * NN + j4;

    float4 v  = *(const float4*)(S + off);
    float4 mx = *(const float4*)(cmax  + b * NN + j4);
    float4 rs = *(const float4*)(crsum + b * NN + j4);
    float a0 = __expf(v.x - mx.x) * rs.x;
    float a1 = __expf(v.y - mx.y) * rs.y;
    float a2 = __expf(v.z - mx.z) * rs.z;
    float a3 = __expf(v.w - mx.w) * rs.w;
    __nv_bfloat16 h0 = __float2bfloat16(a0), h1 = __float2bfloat16(a1);
    __nv_bfloat16 h2 = __float2bfloat16(a2), h3 = __float2bfloat16(a3);
    *(__nv_bfloat162*)(ah + off)     = __nv_bfloat162(h0, h1);
    *(__nv_bfloat162*)(ah + off + 2) = __nv_bfloat162(h2, h3);
    *(__nv_bfloat162*)(al + off)     = __nv_bfloat162(__float2bfloat16(a0 - __bfloat162float(h0)),
                                                      __float2bfloat16(a1 - __bfloat162float(h1)));
    *(__nv_bfloat162*)(al + off + 2) = __nv_bfloat162(__float2bfloat16(a2 - __bfloat162float(h2)),
                                                      __float2bfloat16(a3 - __bfloat162float(h3)));
}

// ---------------- launch ----------------
extern "C" void kernel_launch(void* const* d_in, const int* in_sizes, int n_in,
                              void* d_out, int out_size)
{
    const float* X    = (const float*)d_in[0];
    const float* W    = (const float*)d_in[1];
    const float* bvec = (const float*)d_in[2];
    // gamma (d_in[3]) cancels under softmax — unused.
    float* out = (float*)d_out;

    __nv_bfloat16 *xh, *xl, *wh, *wl, *qh, *ql, *ah, *al;
    float *s, *cmax, *csum;
    cudaGetSymbolAddress((void**)&xh, g_xh);  cudaGetSymbolAddress((void**)&xl, g_xl);
    cudaGetSymbolAddress((void**)&wh, g_wh);  cudaGetSymbolAddress((void**)&wl, g_wl);
    cudaGetSymbolAddress((void**)&qh, g_qh);  cudaGetSymbolAddress((void**)&ql, g_ql);
    cudaGetSymbolAddress((void**)&ah, g_ah);  cudaGetSymbolAddress((void**)&al, g_al);
    cudaGetSymbolAddress((void**)&s,  g_s);
    cudaGetSymbolAddress((void**)&cmax, g_cmax);
    cudaGetSymbolAddress((void**)&csum, g_csum);

    const int smem = STAGES * STAGE_BYTES;   // 96 KB
    cudaFuncSetAttribute(gemm_mma, cudaFuncAttributeMaxDynamicSharedMemorySize, smem);

    // split inputs into hi/lo bf16
    split_hl<<<(BATCH * NN * EE / 4) / 256, 256>>>(X, xh, xl);
    split_hl<<<(EE * EE / 4) / 256, 256>>>(W, wh, wl);

    const long long sXE = (long long)NN * EE;
    const long long sNN = (long long)NN * NN;

    // GEMM1: Q = X W^T + b  -> hi/lo bf16 (qh, ql).   M = B*N = 16384.
    gemm_mma<<<dim3(EE / BN, (BATCH * NN) / BM, 1), 256, smem>>>(
        xh, xl, xh, wh, wh, wl, 0, 0, 0,
        nullptr, qh, ql, bvec, 1);

    // GEMM2: S[b] = Q[b] X[b]^T  (fp32)
    gemm_mma<<<dim3(NN / BN, NN / BM, BATCH), 256, smem>>>(
        qh, ql, qh, xh, xh, xl, sXE, sXE, sNN,
        s, nullptr, nullptr, nullptr, 0);

    // softmax over axis=1 (columns), write split attn
    col_stats<<<dim3(NN / 256, BATCH), 256>>>(s, cmax, csum);
    col_norm_split<<<dim3((NN * NN / 4) / 256, BATCH), 256>>>(s, cmax, csum, ah, al);

    // GEMM3: out[b] = X[b] Attn[b]^T  (fp32)
    gemm_mma<<<dim3(NN / BN, NN / BM, BATCH), 256, smem>>>(
        xh, xl, xh, ah, ah, al, sXE, sNN, sNN,
        out, nullptr, nullptr, nullptr, 0);
}

// round 4
// speedup vs baseline: 2.8204x; 1.1398x over previous
#include <cuda_runtime.h>
#include <cuda_bf16.h>
#include <cstdint>

#define BATCH 8
#define NN 2048
#define EE 2048

#define BM 256
#define BN 128
#define BK 64
#define STAGES 4
#define STAGE_BYTES 49152       // A: 256x128B (32KB) + B: 128x128B (16KB)
#define NBK 96                  // 3 phases x 32 k-blocks of 64

// ---------------- scratch globals (no cudaMalloc allowed) ----------------
__device__ __align__(256) __nv_bfloat16 g_xh[(size_t)BATCH * NN * EE];
__device__ __align__(256) __nv_bfloat16 g_xl[(size_t)BATCH * NN * EE];
__device__ __align__(256) __nv_bfloat16 g_wh[(size_t)EE * EE];
__device__ __align__(256) __nv_bfloat16 g_wl[(size_t)EE * EE];
__device__ __align__(256) __nv_bfloat16 g_qh[(size_t)BATCH * NN * EE];
__device__ __align__(256) __nv_bfloat16 g_ql[(size_t)BATCH * NN * EE];
__device__ __align__(256) __nv_bfloat16 g_ah[(size_t)BATCH * NN * NN];
__device__ __align__(256) __nv_bfloat16 g_al[(size_t)BATCH * NN * NN];
__device__ __align__(256) float         g_s [(size_t)BATCH * NN * NN];
__device__ __align__(256) float         g_cmax[BATCH * NN];
__device__ __align__(256) float         g_csum[BATCH * NN];

// ---------------- helpers ----------------
__device__ __forceinline__ uint32_t smem_u32(const void* p) {
    uint32_t a;
    asm("{ .reg .u64 t; cvta.to.shared.u64 t, %1; cvt.u32.u64 %0, t; }" : "=r"(a) : "l"(p));
    return a;
}
__device__ __forceinline__ void cp16(uint32_t s, const void* g) {
    asm volatile("cp.async.cg.shared.global [%0], [%1], 16;" :: "r"(s), "l"(g) : "memory");
}
__device__ __forceinline__ void cp_commit() {
    asm volatile("cp.async.commit_group;" ::: "memory");
}
template <int N> __device__ __forceinline__ void cp_wait() {
    asm volatile("cp.async.wait_group %0;" :: "n"(N) : "memory");
}
__device__ __forceinline__ void ldm4(uint32_t* r, uint32_t a) {
    asm volatile("ldmatrix.sync.aligned.m8n8.x4.shared.b16 {%0,%1,%2,%3}, [%4];"
                 : "=r"(r[0]), "=r"(r[1]), "=r"(r[2]), "=r"(r[3]) : "r"(a));
}
__device__ __forceinline__ void mma16816(float* c, const uint32_t* a, uint32_t b0, uint32_t b1) {
    asm volatile(
        "mma.sync.aligned.m16n8k16.row.col.f32.bf16.bf16.f32 "
        "{%0,%1,%2,%3}, {%4,%5,%6,%7}, {%8,%9}, {%0,%1,%2,%3};"
        : "+f"(c[0]), "+f"(c[1]), "+f"(c[2]), "+f"(c[3])
        : "r"(a[0]), "r"(a[1]), "r"(a[2]), "r"(a[3]), "r"(b0), "r"(b1));
}

// ---------------- tensor-core GEMM: C[256x128 tile] = A @ B^T, 3-phase bf16 split ----
// Phases: A (p0,p1,p2) x B (p0,p1,p2); all matrices [rows, 2048] bf16, k-contiguous.
// mode 0: write fp32 to outF. mode 1: add bias, split-store hi/lo bf16 to outH/outL.
__global__ __launch_bounds__(256, 1)
void gemm_mma(const __nv_bfloat16* pA0, const __nv_bfloat16* pA1, const __nv_bfloat16* pA2,
              const __nv_bfloat16* pB0, const __nv_bfloat16* pB1, const __nv_bfloat16* pB2,
              long long aBatch, long long bBatch, long long cBatch,
              float* outF, __nv_bfloat16* outH, __nv_bfloat16* outL,
              const float* __restrict__ bias, int mode)
{
    extern __shared__ __align__(128) char smem[];
    const uint32_t stg0 = smem_u32(smem);
    const int tid  = threadIdx.x;
    const int lane = tid & 31;
    const int warp = tid >> 5;
    const int row0 = blockIdx.y * BM;
    const int col0 = blockIdx.x * BN;
    const int z    = blockIdx.z;

    // -------- global->smem producer mapping (all 256 threads) --------
    const int lr = tid >> 3;        // 0..31 row group
    const int lc = tid & 7;         // 16B chunk within 128B row
    const uint32_t so = (uint32_t)(lr * 128 + ((lc ^ (lr & 7)) << 4));

    const __nv_bfloat16* pA[3] = {pA0, pA1, pA2};
    const __nv_bfloat16* pB[3] = {pB0, pB1, pB2};
    const char* gA[3]; const char* gB[3];
#pragma unroll
    for (int p = 0; p < 3; p++) {
        gA[p] = (const char*)(pA[p] + (size_t)z * (size_t)aBatch + (size_t)(row0 + lr) * EE) + lc * 16;
        gB[p] = (const char*)(pB[p] + (size_t)z * (size_t)bBatch + (size_t)(col0 + lr) * EE) + lc * 16;
    }

    // -------- mma fragment addressing precompute --------
    const int wm  = warp & 3;            // 4 warps down M (64 rows each)
    const int wn  = warp >> 2;           // 2 warps across N (64 cols each)
    const int m0w = wm * 64;
    const int n0w = wn * 64;
    const uint32_t aRow  = (uint32_t)(m0w + (lane & 15));
    const uint32_t aBase = aRow * 128;
    const uint32_t aXor  = aRow & 7;
    const uint32_t ac0   = (uint32_t)(lane >> 4);
    const uint32_t bRow  = (uint32_t)(n0w + ((lane >> 4) << 3) + (lane & 7));
    const uint32_t bBase = 32768u + bRow * 128;
    const uint32_t bXor  = (uint32_t)(lane & 7);
    const uint32_t bc0   = (uint32_t)((lane >> 3) & 1);

    float acc[4][8][4] = {};

    // -------- pipeline --------
    auto load_stage = [&](int s, int kb) {
        const int p = kb >> 5;
        const uint32_t koff = (uint32_t)(kb & 31) * 128;
        const uint32_t dstA = stg0 + (uint32_t)s * STAGE_BYTES + so;
        const uint32_t dstB = dstA + 32768u;
        const char* a = gA[p] + koff;
        const char* b = gB[p] + koff;
#pragma unroll
        for (int i = 0; i < 8; i++)
            cp16(dstA + i * 4096u, a + (size_t)i * 131072);   // A: 8 x 32 rows
#pragma unroll
        for (int i = 0; i < 4; i++)
            cp16(dstB + i * 4096u, b + (size_t)i * 131072);   // B: 4 x 32 rows
        cp_commit();
    };

    load_stage(0, 0);
    load_stage(1, 1);
    load_stage(2, 2);

    for (int kb = 0; kb < NBK; kb++) {
        if (kb <= NBK - 3)      cp_wait<2>();
        else if (kb == NBK - 2) cp_wait<1>();
        else                    cp_wait<0>();
        __syncthreads();
        if (kb + 3 < NBK) load_stage((kb + 3) & 3, kb + 3);

        const uint32_t sb = stg0 + (uint32_t)(kb & 3) * STAGE_BYTES;
#pragma unroll
        for (int ks = 0; ks < 4; ks++) {
            uint32_t af[4][4], bf[4][4];
#pragma unroll
            for (int mt = 0; mt < 4; mt++)
                ldm4(af[mt], sb + aBase + mt * 2048u + ((((uint32_t)ks * 2 + ac0) ^ aXor) << 4));
#pragma unroll
            for (int np = 0; np < 4; np++)
                ldm4(bf[np], sb + bBase + np * 2048u + ((((uint32_t)ks * 2 + bc0) ^ bXor) << 4));
#pragma unroll
            for (int mt = 0; mt < 4; mt++)
#pragma unroll
                for (int np = 0; np < 4; np++) {
                    mma16816(acc[mt][np * 2],     af[mt], bf[np][0], bf[np][1]);
                    mma16816(acc[mt][np * 2 + 1], af[mt], bf[np][2], bf[np][3]);
                }
        }
    }

    // -------- epilogue --------
    const int g  = lane >> 2;
    const int tg = lane & 3;
    if (mode == 0) {
        float* base = outF + (size_t)z * (size_t)cBatch;
#pragma unroll
        for (int mt = 0; mt < 4; mt++) {
            const int rg = row0 + m0w + mt * 16 + g;
#pragma unroll
            for (int nt = 0; nt < 8; nt++) {
                const int cg = col0 + n0w + nt * 8 + 2 * tg;
                *(float2*)(base + (size_t)rg * 2048 + cg)       = make_float2(acc[mt][nt][0], acc[mt][nt][1]);
                *(float2*)(base + (size_t)(rg + 8) * 2048 + cg) = make_float2(acc[mt][nt][2], acc[mt][nt][3]);
            }
        }
    } else {
#pragma unroll
        for (int mt = 0; mt < 4; mt++) {
            const int rg = row0 + m0w + mt * 16 + g;
#pragma unroll
            for (int nt = 0; nt < 8; nt++) {
                const int cg = col0 + n0w + nt * 8 + 2 * tg;
                const float b0 = __ldg(bias + cg), b1 = __ldg(bias + cg + 1);
                float v[4] = {acc[mt][nt][0] + b0, acc[mt][nt][1] + b1,
                              acc[mt][nt][2] + b0, acc[mt][nt][3] + b1};
                __nv_bfloat16 h0 = __float2bfloat16(v[0]), h1 = __float2bfloat16(v[1]);
                __nv_bfloat16 h2 = __float2bfloat16(v[2]), h3 = __float2bfloat16(v[3]);
                __nv_bfloat16 l0 = __float2bfloat16(v[0] - __bfloat162float(h0));
                __nv_bfloat16 l1 = __float2bfloat16(v[1] - __bfloat162float(h1));
                __nv_bfloat16 l2 = __float2bfloat16(v[2] - __bfloat162float(h2));
                __nv_bfloat16 l3 = __float2bfloat16(v[3] - __bfloat162float(h3));
                *(__nv_bfloat162*)(outH + (size_t)rg * 2048 + cg)       = __nv_bfloat162(h0, h1);
                *(__nv_bfloat162*)(outL + (size_t)rg * 2048 + cg)       = __nv_bfloat162(l0, l1);
                *(__nv_bfloat162*)(outH + (size_t)(rg + 8) * 2048 + cg) = __nv_bfloat162(h2, h3);
                *(__nv_bfloat162*)(outL + (size_t)(rg + 8) * 2048 + cg) = __nv_bfloat162(l2, l3);
            }
        }
    }
}

// ---------------- fp32 -> (bf16 hi, bf16 lo) split ----------------
__global__ void split_hl(const float* __restrict__ src,
                         __nv_bfloat16* __restrict__ h, __nv_bfloat16* __restrict__ l)
{
    const size_t i = ((size_t)blockIdx.x * blockDim.x + threadIdx.x) * 4;
    float4 v = *(const float4*)(src + i);
    __nv_bfloat16 h0 = __float2bfloat16(v.x), h1 = __float2bfloat16(v.y);
    __nv_bfloat16 h2 = __float2bfloat16(v.z), h3 = __float2bfloat16(v.w);
    *(__nv_bfloat162*)(h + i)     = __nv_bfloat162(h0, h1);
    *(__nv_bfloat162*)(h + i + 2) = __nv_bfloat162(h2, h3);
    *(__nv_bfloat162*)(l + i)     = __nv_bfloat162(__float2bfloat16(v.x - __bfloat162float(h0)),
                                                   __float2bfloat16(v.y - __bfloat162float(h1)));
    *(__nv_bfloat162*)(l + i + 2) = __nv_bfloat162(__float2bfloat16(v.z - __bfloat162float(h2)),
                                                   __float2bfloat16(v.w - __bfloat162float(h3)));
}

// ---------------- column softmax (axis=1) ----------------
__global__ void col_stats(const float* __restrict__ S,
                          float* __restrict__ cmax, float* __restrict__ crsum)
{
    const int b = blockIdx.y;
    const int j = blockIdx.x * blockDim.x + threadIdx.x;
    const float* Sb = S + (size_t)b * NN * NN + j;
    float m[4] = {-1e30f, -1e30f, -1e30f, -1e30f};
    float s[4] = {0.f, 0.f, 0.f, 0.f};
    for (int i = 0; i < NN; i += 4) {
#pragma unroll
        for (int u = 0; u < 4; u++) {
            float v  = Sb[(size_t)(i + u) * NN];
            float nm = fmaxf(m[u], v);
            s[u] = s[u] * __expf(m[u] - nm) + __expf(v - nm);
            m[u] = nm;
        }
    }
    float M = fmaxf(fmaxf(m[0], m[1]), fmaxf(m[2], m[3]));
    float T = s[0] * __expf(m[0] - M) + s[1] * __expf(m[1] - M)
            + s[2] * __expf(m[2] - M) + s[3] * __expf(m[3] - M);
    cmax[b * NN + j]  = M;
    crsum[b * NN + j] = 1.0f / T;
}

__global__ void col_norm_split(const float* __restrict__ S,
                               const float* __restrict__ cmax, const float* __restrict__ crsum,
                               __nv_bfloat16* __restrict__ ah, __nv_bfloat16* __restrict__ al)
{
    const int b   = blockIdx.y;
    const int lin = blockIdx.x * blockDim.x + threadIdx.x;
    const int i   = lin >> 9;
    const int j4  = (lin & 511) << 2;
    const size_t off = (size_t)b * NN * NN + (size_t)i * NN + j4;

    float4 v  = *(const float4*)(S + off);
    float4 mx = *(const float4*)(cmax  + b * NN + j4);
    float4 rs = *(const float4*)(crsum + b * NN + j4);
    float a0 = __expf(v.x - mx.x) * rs.x;
    float a1 = __expf(v.y - mx.y) * rs.y;
    float a2 = __expf(v.z - mx.z) * rs.z;
    float a3 = __expf(v.w - mx.w) * rs.w;
    __nv_bfloat16 h0 = __float2bfloat16(a0), h1 = __float2bfloat16(a1);
    __nv_bfloat16 h2 = __float2bfloat16(a2), h3 = __float2bfloat16(a3);
    *(__nv_bfloat162*)(ah + off)     = __nv_bfloat162(h0, h1);
    *(__nv_bfloat162*)(ah + off + 2) = __nv_bfloat162(h2, h3);
    *(__nv_bfloat162*)(al + off)     = __nv_bfloat162(__float2bfloat16(a0 - __bfloat162float(h0)),
                                                      __float2bfloat16(a1 - __bfloat162float(h1)));
    *(__nv_bfloat162*)(al + off + 2) = __nv_bfloat162(__float2bfloat16(a2 - __bfloat162float(h2)),
                                                      __float2bfloat16(a3 - __bfloat162float(h3)));
}

// ---------------- launch ----------------
extern "C" void kernel_launch(void* const* d_in, const int* in_sizes, int n_in,
                              void* d_out, int out_size)
{
    const float* X    = (const float*)d_in[0];
    const float* W    = (const float*)d_in[1];
    const float* bvec = (const float*)d_in[2];
    // gamma (d_in[3]) cancels under softmax — unused.
    float* out = (float*)d_out;

    __nv_bfloat16 *xh, *xl, *wh, *wl, *qh, *ql, *ah, *al;
    float *s, *cmax, *csum;
    cudaGetSymbolAddress((void**)&xh, g_xh);  cudaGetSymbolAddress((void**)&xl, g_xl);
    cudaGetSymbolAddress((void**)&wh, g_wh);  cudaGetSymbolAddress((void**)&wl, g_wl);
    cudaGetSymbolAddress((void**)&qh, g_qh);  cudaGetSymbolAddress((void**)&ql, g_ql);
    cudaGetSymbolAddress((void**)&ah, g_ah);  cudaGetSymbolAddress((void**)&al, g_al);
    cudaGetSymbolAddress((void**)&s,  g_s);
    cudaGetSymbolAddress((void**)&cmax, g_cmax);
    cudaGetSymbolAddress((void**)&csum, g_csum);

    const int smem = STAGES * STAGE_BYTES;   // 192 KB
    cudaFuncSetAttribute(gemm_mma, cudaFuncAttributeMaxDynamicSharedMemorySize, smem);

    // split inputs into hi/lo bf16
    split_hl<<<(BATCH * NN * EE / 4) / 256, 256>>>(X, xh, xl);
    split_hl<<<(EE * EE / 4) / 256, 256>>>(W, wh, wl);

    const long long sXE = (long long)NN * EE;
    const long long sNN = (long long)NN * NN;

    // GEMM1: Q = X W^T + b  -> hi/lo bf16 (qh, ql).   M = B*N = 16384.
    gemm_mma<<<dim3(EE / BN, (BATCH * NN) / BM, 1), 256, smem>>>(
        xh, xl, xh, wh, wh, wl, 0, 0, 0,
        nullptr, qh, ql, bvec, 1);

    // GEMM2: S[b] = Q[b] X[b]^T  (fp32)
    gemm_mma<<<dim3(NN / BN, NN / BM, BATCH), 256, smem>>>(
        qh, ql, qh, xh, xh, xl, sXE, sXE, sNN,
        s, nullptr, nullptr, nullptr, 0);

    // softmax over axis=1 (columns), write split attn
    col_stats<<<dim3(NN / 256, BATCH), 256>>>(s, cmax, csum);
    col_norm_split<<<dim3((NN * NN / 4) / 256, BATCH), 256>>>(s, cmax, csum, ah, al);

    // GEMM3: out[b] = X[b] Attn[b]^T  (fp32)
    gemm_mma<<<dim3(NN / BN, NN / BM, BATCH), 256, smem>>>(
        xh, xl, xh, ah, ah, al, sXE, sNN, sNN,
        out, nullptr, nullptr, nullptr, 0);
}

// round 5
// speedup vs baseline: 2.8891x; 1.0244x over previous
#include <cuda_runtime.h>
#include <cuda_bf16.h>
#include <cstdint>

#define BATCH 8
#define NN 2048
#define EE 2048

#define BM 256
#define BN 128
#define BK 64
#define STAGES 4
#define STAGE_BYTES 49152       // A: 256x128B (32KB) + B: 128x128B (16KB)
#define NBK 96                  // 3 phases x 32 k-blocks of 64

// ---------------- scratch globals (no cudaMalloc allowed) ----------------
__device__ __align__(256) __nv_bfloat16 g_xh[(size_t)BATCH * NN * EE];
__device__ __align__(256) __nv_bfloat16 g_xl[(size_t)BATCH * NN * EE];
__device__ __align__(256) __nv_bfloat16 g_wh[(size_t)EE * EE];
__device__ __align__(256) __nv_bfloat16 g_wl[(size_t)EE * EE];
__device__ __align__(256) __nv_bfloat16 g_qh[(size_t)BATCH * NN * EE];
__device__ __align__(256) __nv_bfloat16 g_ql[(size_t)BATCH * NN * EE];
__device__ __align__(256) __nv_bfloat16 g_ah[(size_t)BATCH * NN * NN];
__device__ __align__(256) __nv_bfloat16 g_al[(size_t)BATCH * NN * NN];
__device__ __align__(256) float         g_s [(size_t)BATCH * NN * NN];
__device__ __align__(256) float         g_cmax[BATCH * NN];
__device__ __align__(256) float         g_csum[BATCH * NN];

// ---------------- helpers ----------------
__device__ __forceinline__ uint32_t smem_u32(const void* p) {
    uint32_t a;
    asm("{ .reg .u64 t; cvta.to.shared.u64 t, %1; cvt.u32.u64 %0, t; }" : "=r"(a) : "l"(p));
    return a;
}
__device__ __forceinline__ void cp16(uint32_t s, const void* g) {
    asm volatile("cp.async.cg.shared.global [%0], [%1], 16;" :: "r"(s), "l"(g) : "memory");
}
__device__ __forceinline__ void cp_commit() {
    asm volatile("cp.async.commit_group;" ::: "memory");
}
template <int N> __device__ __forceinline__ void cp_wait() {
    asm volatile("cp.async.wait_group %0;" :: "n"(N) : "memory");
}
__device__ __forceinline__ void ldm4(uint32_t* r, uint32_t a) {
    asm volatile("ldmatrix.sync.aligned.m8n8.x4.shared.b16 {%0,%1,%2,%3}, [%4];"
                 : "=r"(r[0]), "=r"(r[1]), "=r"(r[2]), "=r"(r[3]) : "r"(a));
}
__device__ __forceinline__ void mma16816(float* c, const uint32_t* a, uint32_t b0, uint32_t b1) {
    asm volatile(
        "mma.sync.aligned.m16n8k16.row.col.f32.bf16.bf16.f32 "
        "{%0,%1,%2,%3}, {%4,%5,%6,%7}, {%8,%9}, {%0,%1,%2,%3};"
        : "+f"(c[0]), "+f"(c[1]), "+f"(c[2]), "+f"(c[3])
        : "r"(a[0]), "r"(a[1]), "r"(a[2]), "r"(a[3]), "r"(b0), "r"(b1));
}

// ---------------- tensor-core GEMM: C[256x128 tile] = A @ B^T, 3-phase bf16 split ----
// Phases: A (p0,p1,p2) x B (p0,p1,p2); all matrices [rows, 2048] bf16, k-contiguous.
// mode 0: write fp32 to outF. mode 1: split-store hi/lo bf16 to outH/outL.
__global__ __launch_bounds__(256, 1)
void gemm_mma(const __nv_bfloat16* pA0, const __nv_bfloat16* pA1, const __nv_bfloat16* pA2,
              const __nv_bfloat16* pB0, const __nv_bfloat16* pB1, const __nv_bfloat16* pB2,
              long long aBatch, long long bBatch, long long cBatch,
              float* outF, __nv_bfloat16* outH, __nv_bfloat16* outL, int mode)
{
    extern __shared__ __align__(128) char smem[];
    const uint32_t stg0 = smem_u32(smem);
    const int tid  = threadIdx.x;
    const int lane = tid & 31;
    const int warp = tid >> 5;
    const int row0 = blockIdx.y * BM;
    const int col0 = blockIdx.x * BN;
    const int z    = blockIdx.z;

    // -------- global->smem producer mapping (all 256 threads) --------
    const int lr = tid >> 3;        // 0..31 row group
    const int lc = tid & 7;         // 16B chunk within 128B row
    const uint32_t so = (uint32_t)(lr * 128 + ((lc ^ (lr & 7)) << 4));

    const __nv_bfloat16* pA[3] = {pA0, pA1, pA2};
    const __nv_bfloat16* pB[3] = {pB0, pB1, pB2};
    const char* gA[3]; const char* gB[3];
#pragma unroll
    for (int p = 0; p < 3; p++) {
        gA[p] = (const char*)(pA[p] + (size_t)z * (size_t)aBatch + (size_t)(row0 + lr) * EE) + lc * 16;
        gB[p] = (const char*)(pB[p] + (size_t)z * (size_t)bBatch + (size_t)(col0 + lr) * EE) + lc * 16;
    }

    // -------- mma fragment addressing precompute --------
    const int wm  = warp & 3;            // 4 warps down M (64 rows each)
    const int wn  = warp >> 2;           // 2 warps across N (64 cols each)
    const int m0w = wm * 64;
    const int n0w = wn * 64;
    const uint32_t aRow  = (uint32_t)(m0w + (lane & 15));
    const uint32_t aBase = aRow * 128;
    const uint32_t aXor  = aRow & 7;
    const uint32_t ac0   = (uint32_t)(lane >> 4);
    const uint32_t bRow  = (uint32_t)(n0w + ((lane >> 4) << 3) + (lane & 7));
    const uint32_t bBase = 32768u + bRow * 128;
    const uint32_t bXor  = (uint32_t)(lane & 7);
    const uint32_t bc0   = (uint32_t)((lane >> 3) & 1);
    // same-SMSP warp pairs differ in wn: stagger their ks traversal to decorrelate
    // ldmatrix bursts from MMA streams.
    const uint32_t ksrot = (uint32_t)(wn << 1);

    float acc[4][8][4] = {};

    // -------- pipeline --------
    // one quarter of a stage load (3 cp16 per thread); part 3 commits the group
    auto load_chunk = [&](int s, int kb, int part) {
        const int p = kb >> 5;
        const uint32_t koff = (uint32_t)(kb & 31) * 128;
        const uint32_t dstA = stg0 + (uint32_t)s * STAGE_BYTES + so;
        const uint32_t dstB = dstA + 32768u;
        const char* a = gA[p] + koff;
        const char* b = gB[p] + koff;
        cp16(dstA + (uint32_t)(part * 2)     * 4096u, a + (size_t)(part * 2)     * 131072);
        cp16(dstA + (uint32_t)(part * 2 + 1) * 4096u, a + (size_t)(part * 2 + 1) * 131072);
        cp16(dstB + (uint32_t)part           * 4096u, b + (size_t)part           * 131072);
        if (part == 3) cp_commit();
    };
    auto load_stage = [&](int s, int kb) {
#pragma unroll
        for (int part = 0; part < 4; part++) load_chunk(s, kb, part);
    };

    load_stage(0, 0);
    load_stage(1, 1);
    load_stage(2, 2);

    for (int kb = 0; kb < NBK; kb++) {
        if (kb <= NBK - 3)      cp_wait<2>();
        else if (kb == NBK - 2) cp_wait<1>();
        else                    cp_wait<0>();
        __syncthreads();

        const bool doLoad = (kb + 3 < NBK);
        const uint32_t sb = stg0 + (uint32_t)(kb & 3) * STAGE_BYTES;
#pragma unroll
        for (int ks = 0; ks < 4; ks++) {
            // producer work spread across the ks iterations (plain ks order per thread)
            if (doLoad) load_chunk((kb + 3) & 3, kb + 3, ks);

            const uint32_t ke = ((uint32_t)ks + ksrot) & 3;   // staggered consume order
            uint32_t af[4][4], bf[4][4];
#pragma unroll
            for (int mt = 0; mt < 4; mt++)
                ldm4(af[mt], sb + aBase + mt * 2048u + (((ke * 2 + ac0) ^ aXor) << 4));
#pragma unroll
            for (int np = 0; np < 4; np++)
                ldm4(bf[np], sb + bBase + np * 2048u + (((ke * 2 + bc0) ^ bXor) << 4));
#pragma unroll
            for (int mt = 0; mt < 4; mt++)
#pragma unroll
                for (int np = 0; np < 4; np++) {
                    mma16816(acc[mt][np * 2],     af[mt], bf[np][0], bf[np][1]);
                    mma16816(acc[mt][np * 2 + 1], af[mt], bf[np][2], bf[np][3]);
                }
        }
    }

    // -------- epilogue --------
    const int g  = lane >> 2;
    const int tg = lane & 3;
    if (mode == 0) {
        float* base = outF + (size_t)z * (size_t)cBatch;
#pragma unroll
        for (int mt = 0; mt < 4; mt++) {
            const int rg = row0 + m0w + mt * 16 + g;
#pragma unroll
            for (int nt = 0; nt < 8; nt++) {
                const int cg = col0 + n0w + nt * 8 + 2 * tg;
                *(float2*)(base + (size_t)rg * 2048 + cg)       = make_float2(acc[mt][nt][0], acc[mt][nt][1]);
                *(float2*)(base + (size_t)(rg + 8) * 2048 + cg) = make_float2(acc[mt][nt][2], acc[mt][nt][3]);
            }
        }
    } else {
#pragma unroll
        for (int mt = 0; mt < 4; mt++) {
            const int rg = row0 + m0w + mt * 16 + g;
#pragma unroll
            for (int nt = 0; nt < 8; nt++) {
                const int cg = col0 + n0w + nt * 8 + 2 * tg;
                float v[4] = {acc[mt][nt][0], acc[mt][nt][1], acc[mt][nt][2], acc[mt][nt][3]};
                __nv_bfloat16 h0 = __float2bfloat16(v[0]), h1 = __float2bfloat16(v[1]);
                __nv_bfloat16 h2 = __float2bfloat16(v[2]), h3 = __float2bfloat16(v[3]);
                __nv_bfloat16 l0 = __float2bfloat16(v[0] - __bfloat162float(h0));
                __nv_bfloat16 l1 = __float2bfloat16(v[1] - __bfloat162float(h1));
                __nv_bfloat16 l2 = __float2bfloat16(v[2] - __bfloat162float(h2));
                __nv_bfloat16 l3 = __float2bfloat16(v[3] - __bfloat162float(h3));
                *(__nv_bfloat162*)(outH + (size_t)rg * 2048 + cg)       = __nv_bfloat162(h0, h1);
                *(__nv_bfloat162*)(outL + (size_t)rg * 2048 + cg)       = __nv_bfloat162(l0, l1);
                *(__nv_bfloat162*)(outH + (size_t)(rg + 8) * 2048 + cg) = __nv_bfloat162(h2, h3);
                *(__nv_bfloat162*)(outL + (size_t)(rg + 8) * 2048 + cg) = __nv_bfloat162(l2, l3);
            }
        }
    }
}

// ---------------- fp32 -> (bf16 hi, bf16 lo) split ----------------
__global__ void split_hl(const float* __restrict__ src,
                         __nv_bfloat16* __restrict__ h, __nv_bfloat16* __restrict__ l)
{
    const size_t i = ((size_t)blockIdx.x * blockDim.x + threadIdx.x) * 4;
    float4 v = *(const float4*)(src + i);
    __nv_bfloat16 h0 = __float2bfloat16(v.x), h1 = __float2bfloat16(v.y);
    __nv_bfloat16 h2 = __float2bfloat16(v.z), h3 = __float2bfloat16(v.w);
    *(__nv_bfloat162*)(h + i)     = __nv_bfloat162(h0, h1);
    *(__nv_bfloat162*)(h + i + 2) = __nv_bfloat162(h2, h3);
    *(__nv_bfloat162*)(l + i)     = __nv_bfloat162(__float2bfloat16(v.x - __bfloat162float(h0)),
                                                   __float2bfloat16(v.y - __bfloat162float(h1)));
    *(__nv_bfloat162*)(l + i + 2) = __nv_bfloat162(__float2bfloat16(v.z - __bfloat162float(h2)),
                                                   __float2bfloat16(v.w - __bfloat162float(h3)));
}

// ---------------- column softmax (axis=1) ----------------
__global__ void col_stats(const float* __restrict__ S,
                          float* __restrict__ cmax, float* __restrict__ crsum)
{
    const int b = blockIdx.y;
    const int j = blockIdx.x * blockDim.x + threadIdx.x;
    const float* Sb = S + (size_t)b * NN * NN + j;
    float m[4] = {-1e30f, -1e30f, -1e30f, -1e30f};
    float s[4] = {0.f, 0.f, 0.f, 0.f};
    for (int i = 0; i < NN; i += 4) {
#pragma unroll
        for (int u = 0; u < 4; u++) {
            float v  = Sb[(size_t)(i + u) * NN];
            float nm = fmaxf(m[u], v);
            s[u] = s[u] * __expf(m[u] - nm) + __expf(v - nm);
            m[u] = nm;
        }
    }
    float M = fmaxf(fmaxf(m[0], m[1]), fmaxf(m[2], m[3]));
    float T = s[0] * __expf(m[0] - M) + s[1] * __expf(m[1] - M)
            + s[2] * __expf(m[2] - M) + s[3] * __expf(m[3] - M);
    cmax[b * NN + j]  = M;
    crsum[b * NN + j] = 1.0f / T;
}

__global__ void col_norm_split(const float* __restrict__ S,
                               const float* __restrict__ cmax, const float* __restrict__ crsum,
                               __nv_bfloat16* __restrict__ ah, __nv_bfloat16* __restrict__ al)
{
    const int b   = blockIdx.y;
    const int lin = blockIdx.x * blockDim.x + threadIdx.x;
    const int i   = lin >> 9;
    const int j4  = (lin & 511) << 2;
    const size_t off = (size_t)b * NN * NN + (size_t)i * NN + j4;

    float4 v  = *(const float4*)(S + off);
    float4 mx = *(const float4*)(cmax  + b * NN + j4);
    float4 rs = *(const float4*)(crsum + b * NN + j4);
    float a0 = __expf(v.x - mx.x) * rs.x;
    float a1 = __expf(v.y - mx.y) * rs.y;
    float a2 = __expf(v.z - mx.z) * rs.z;
    float a3 = __expf(v.w - mx.w) * rs.w;
    __nv_bfloat16 h0 = __float2bfloat16(a0), h1 = __float2bfloat16(a1);
    __nv_bfloat16 h2 = __float2bfloat16(a2), h3 = __float2bfloat16(a3);
    *(__nv_bfloat162*)(ah + off)     = __nv_bfloat162(h0, h1);
    *(__nv_bfloat162*)(ah + off + 2) = __nv_bfloat162(h2, h3);
    *(__nv_bfloat162*)(al + off)     = __nv_bfloat162(__float2bfloat16(a0 - __bfloat162float(h0)),
                                                      __float2bfloat16(a1 - __bfloat162float(h1)));
    *(__nv_bfloat162*)(al + off + 2) = __nv_bfloat162(__float2bfloat16(a2 - __bfloat162float(h2)),
                                                      __float2bfloat16(a3 - __bfloat162float(h3)));
}

// ---------------- launch ----------------
extern "C" void kernel_launch(void* const* d_in, const int* in_sizes, int n_in,
                              void* d_out, int out_size)
{
    const float* X = (const float*)d_in[0];
    const float* W = (const float*)d_in[1];
    // d_in[2] = bias: adds a per-column constant to scores -> cancels in axis-1 softmax.
    // d_in[3] = gamma: scalar constant -> cancels likewise. Both unused.
    float* out = (float*)d_out;

    __nv_bfloat16 *xh, *xl, *wh, *wl, *qh, *ql, *ah, *al;
    float *s, *cmax, *csum;
    cudaGetSymbolAddress((void**)&xh, g_xh);  cudaGetSymbolAddress((void**)&xl, g_xl);
    cudaGetSymbolAddress((void**)&wh, g_wh);  cudaGetSymbolAddress((void**)&wl, g_wl);
    cudaGetSymbolAddress((void**)&qh, g_qh);  cudaGetSymbolAddress((void**)&ql, g_ql);
    cudaGetSymbolAddress((void**)&ah, g_ah);  cudaGetSymbolAddress((void**)&al, g_al);
    cudaGetSymbolAddress((void**)&s,  g_s);
    cudaGetSymbolAddress((void**)&cmax, g_cmax);
    cudaGetSymbolAddress((void**)&csum, g_csum);

    const int smem = STAGES * STAGE_BYTES;   // 192 KB
    cudaFuncSetAttribute(gemm_mma, cudaFuncAttributeMaxDynamicSharedMemorySize, smem);

    // split inputs into hi/lo bf16
    split_hl<<<(BATCH * NN * EE / 4) / 256, 256>>>(X, xh, xl);
    split_hl<<<(EE * EE / 4) / 256, 256>>>(W, wh, wl);

    const long long sXE = (long long)NN * EE;
    const long long sNN = (long long)NN * NN;

    // GEMM1: Q = X W^T  -> hi/lo bf16 (qh, ql).   M = B*N = 16384. (bias dropped: cancels)
    gemm_mma<<<dim3(EE / BN, (BATCH * NN) / BM, 1), 256, smem>>>(
        xh, xl, xh, wh, wh, wl, 0, 0, 0,
        nullptr, qh, ql, 1);

    // GEMM2: S[b] = Q[b] X[b]^T  (fp32)
    gemm_mma<<<dim3(NN / BN, NN / BM, BATCH), 256, smem>>>(
        qh, ql, qh, xh, xh, xl, sXE, sXE, sNN,
        s, nullptr, nullptr, 0);

    // softmax over axis=1 (columns), write split attn
    col_stats<<<dim3(NN / 256, BATCH), 256>>>(s, cmax, csum);
    col_norm_split<<<dim3((NN * NN / 4) / 256, BATCH), 256>>>(s, cmax, csum, ah, al);

    // GEMM3: out[b] = X[b] Attn[b]^T  (fp32)
    gemm_mma<<<dim3(NN / BN, NN / BM, BATCH), 256, smem>>>(
        xh, xl, xh, ah, ah, al, sXE, sNN, sNN,
        out, nullptr, nullptr, 0);
}

// round 6
// speedup vs baseline: 3.2808x; 1.1356x over previous
#include <cuda_runtime.h>
#include <cuda_bf16.h>
#include <cstdint>

#define BATCH 8
#define NN 2048
#define EE 2048

#define BM 256
#define BN 128
#define BK 64
#define STAGES 4
#define STAGE_BYTES 49152       // A: 256x128B (32KB) + B: 128x128B (16KB)
#define NBK 96                  // 3 phases x 32 k-blocks of 64

// ---------------- scratch globals (no cudaMalloc allowed) ----------------
__device__ __align__(256) __nv_bfloat16 g_xh[(size_t)BATCH * NN * EE];
__device__ __align__(256) __nv_bfloat16 g_xl[(size_t)BATCH * NN * EE];
__device__ __align__(256) __nv_bfloat16 g_wh[(size_t)EE * EE];
__device__ __align__(256) __nv_bfloat16 g_wl[(size_t)EE * EE];
__device__ __align__(256) __nv_bfloat16 g_qh[(size_t)BATCH * NN * EE];
__device__ __align__(256) __nv_bfloat16 g_ql[(size_t)BATCH * NN * EE];
__device__ __align__(256) __nv_bfloat16 g_ah[(size_t)BATCH * NN * NN];
__device__ __align__(256) __nv_bfloat16 g_al[(size_t)BATCH * NN * NN];
__device__ __align__(256) float         g_s [(size_t)BATCH * NN * NN];
__device__ __align__(256) float         g_cmax[BATCH * NN];
__device__ __align__(256) float         g_csum[BATCH * NN];

// ---------------- helpers ----------------
__device__ __forceinline__ uint32_t smem_u32(const void* p) {
    uint32_t a;
    asm("{ .reg .u64 t; cvta.to.shared.u64 t, %1; cvt.u32.u64 %0, t; }" : "=r"(a) : "l"(p));
    return a;
}
__device__ __forceinline__ void cp16(uint32_t s, const void* g) {
    asm volatile("cp.async.cg.shared.global [%0], [%1], 16;" :: "r"(s), "l"(g) : "memory");
}
__device__ __forceinline__ void cp_commit() {
    asm volatile("cp.async.commit_group;" ::: "memory");
}
template <int N> __device__ __forceinline__ void cp_wait() {
    asm volatile("cp.async.wait_group %0;" :: "n"(N) : "memory");
}
__device__ __forceinline__ void ldm4(uint32_t* r, uint32_t a) {
    asm volatile("ldmatrix.sync.aligned.m8n8.x4.shared.b16 {%0,%1,%2,%3}, [%4];"
                 : "=r"(r[0]), "=r"(r[1]), "=r"(r[2]), "=r"(r[3]) : "r"(a));
}
__device__ __forceinline__ void mma16816(float* c, const uint32_t* a, uint32_t b0, uint32_t b1) {
    asm volatile(
        "mma.sync.aligned.m16n8k16.row.col.f32.bf16.bf16.f32 "
        "{%0,%1,%2,%3}, {%4,%5,%6,%7}, {%8,%9}, {%0,%1,%2,%3};"
        : "+f"(c[0]), "+f"(c[1]), "+f"(c[2]), "+f"(c[3])
        : "r"(a[0]), "r"(a[1]), "r"(a[2]), "r"(a[3]), "r"(b0), "r"(b1));
}

// ---------------- tensor-core GEMM: C[256x128 tile] = A @ B^T, 3-phase bf16 split ----
// Phases over K'=3*2048: Ah*Bh, Al*Bh, Ah*Bl.
// mode 0: write fp32 to outF. mode 1: split-store hi/lo bf16 to outH/outL.
__global__ __launch_bounds__(256, 1)
void gemm_mma(const __nv_bfloat16* Ah, const __nv_bfloat16* Al,
              const __nv_bfloat16* Bh, const __nv_bfloat16* Bl,
              long long aBatch, long long bBatch, long long cBatch,
              float* outF, __nv_bfloat16* outH, __nv_bfloat16* outL, int mode)
{
    extern __shared__ __align__(128) char smem[];
    const uint32_t stg0 = smem_u32(smem);
    const int tid  = threadIdx.x;
    const int lane = tid & 31;
    const int warp = tid >> 5;
    const int row0 = blockIdx.y * BM;
    const int col0 = blockIdx.x * BN;
    const int z    = blockIdx.z;

    // -------- global->smem producer mapping (all 256 threads) --------
    const int lr = tid >> 3;        // 0..31 row group
    const int lc = tid & 7;         // 16B chunk within 128B row
    const uint32_t so = (uint32_t)(lr * 128 + ((lc ^ (lr & 7)) << 4));

    const char* gAh = (const char*)(Ah + (size_t)z * (size_t)aBatch + (size_t)(row0 + lr) * EE) + lc * 16;
    const char* gAl = (const char*)(Al + (size_t)z * (size_t)aBatch + (size_t)(row0 + lr) * EE) + lc * 16;
    const char* gBh = (const char*)(Bh + (size_t)z * (size_t)bBatch + (size_t)(col0 + lr) * EE) + lc * 16;
    const char* gBl = (const char*)(Bl + (size_t)z * (size_t)bBatch + (size_t)(col0 + lr) * EE) + lc * 16;

    // -------- mma fragment addressing precompute --------
    const int wm  = warp & 3;            // 4 warps down M (64 rows each)
    const int wn  = warp >> 2;           // 2 warps across N (64 cols each)
    const int m0w = wm * 64;
    const int n0w = wn * 64;
    const uint32_t aRow  = (uint32_t)(m0w + (lane & 15));
    const uint32_t aBase = aRow * 128;
    const uint32_t aXor  = aRow & 7;
    const uint32_t ac0   = (uint32_t)(lane >> 4);
    const uint32_t bRow  = (uint32_t)(n0w + ((lane >> 4) << 3) + (lane & 7));
    const uint32_t bBase = 32768u + bRow * 128;
    const uint32_t bXor  = (uint32_t)(lane & 7);
    const uint32_t bc0   = (uint32_t)((lane >> 3) & 1);

    float acc[4][8][4] = {};
    uint32_t af[2][4][4], bf[2][4][4];   // double-buffered fragments

    // one quarter of a stage load (3 cp16 per thread); part 3 commits the group
    auto load_chunk = [&](int s, int kbn, int part) {
        const int p = kbn >> 5;
        const char* a = (p == 1) ? gAl : gAh;
        const char* b = (p == 2) ? gBl : gBh;
        const uint32_t koff = (uint32_t)(kbn & 31) * 128;
        const uint32_t dstA = stg0 + (uint32_t)s * STAGE_BYTES + so;
        const uint32_t dstB = dstA + 32768u;
        cp16(dstA + (uint32_t)(part * 2)     * 4096u, a + koff + (size_t)(part * 2)     * 131072);
        cp16(dstA + (uint32_t)(part * 2 + 1) * 4096u, a + koff + (size_t)(part * 2 + 1) * 131072);
        cp16(dstB + (uint32_t)part           * 4096u, b + koff + (size_t)part           * 131072);
        if (part == 3) cp_commit();
    };
    auto load_stage = [&](int s, int kbn) {
#pragma unroll
        for (int part = 0; part < 4; part++) load_chunk(s, kbn, part);
    };
    // fragment load for one ks into buffer bsel from stage base sb_
    auto ldm_ks = [&](uint32_t sb_, uint32_t ke, int bsel) {
#pragma unroll
        for (int mt = 0; mt < 4; mt++)
            ldm4(af[bsel][mt], sb_ + aBase + mt * 2048u + (((ke * 2 + ac0) ^ aXor) << 4));
#pragma unroll
        for (int np = 0; np < 4; np++)
            ldm4(bf[bsel][np], sb_ + bBase + np * 2048u + (((ke * 2 + bc0) ^ bXor) << 4));
    };

    load_stage(0, 0);
    load_stage(1, 1);
    load_stage(2, 2);
    cp_wait<1>();                 // stages 0 and 1 complete
    __syncthreads();
    ldm_ks(stg0, 0, 0);           // fragments for kb=0, ks=0

    for (int kb = 0; kb < NBK; kb++) {
        const uint32_t sb = stg0 + (uint32_t)(kb & 3) * STAGE_BYTES;
        const bool doLoad = (kb + 3 < NBK);
#pragma unroll
        for (int ks = 0; ks < 4; ks++) {
            if (doLoad) load_chunk((kb + 3) & 3, kb + 3, ks);
            const int cur = ks & 1;
            // prefetch next fragment set into the other buffer
            if (ks < 3)
                ldm_ks(sb, (uint32_t)ks + 1, cur ^ 1);
            else if (kb + 1 < NBK)
                ldm_ks(stg0 + (uint32_t)((kb + 1) & 3) * STAGE_BYTES, 0, cur ^ 1);
#pragma unroll
            for (int mt = 0; mt < 4; mt++)
#pragma unroll
                for (int np = 0; np < 4; np++) {
                    mma16816(acc[mt][np * 2],     af[cur][mt], bf[cur][np][0], bf[cur][np][1]);
                    mma16816(acc[mt][np * 2 + 1], af[cur][mt], bf[cur][np][2], bf[cur][np][3]);
                }
        }
        if (kb + 1 < NBK) {
            if (kb + 3 < NBK) cp_wait<1>(); else cp_wait<0>();
            __syncthreads();
        }
    }

    // -------- epilogue --------
    const int g  = lane >> 2;
    const int tg = lane & 3;
    if (mode == 0) {
        float* base = outF + (size_t)z * (size_t)cBatch;
#pragma unroll
        for (int mt = 0; mt < 4; mt++) {
            const int rg = row0 + m0w + mt * 16 + g;
#pragma unroll
            for (int nt = 0; nt < 8; nt++) {
                const int cg = col0 + n0w + nt * 8 + 2 * tg;
                *(float2*)(base + (size_t)rg * 2048 + cg)       = make_float2(acc[mt][nt][0], acc[mt][nt][1]);
                *(float2*)(base + (size_t)(rg + 8) * 2048 + cg) = make_float2(acc[mt][nt][2], acc[mt][nt][3]);
            }
        }
    } else {
#pragma unroll
        for (int mt = 0; mt < 4; mt++) {
            const int rg = row0 + m0w + mt * 16 + g;
#pragma unroll
            for (int nt = 0; nt < 8; nt++) {
                const int cg = col0 + n0w + nt * 8 + 2 * tg;
                float v[4] = {acc[mt][nt][0], acc[mt][nt][1], acc[mt][nt][2], acc[mt][nt][3]};
                __nv_bfloat16 h0 = __float2bfloat16(v[0]), h1 = __float2bfloat16(v[1]);
                __nv_bfloat16 h2 = __float2bfloat16(v[2]), h3 = __float2bfloat16(v[3]);
                __nv_bfloat16 l0 = __float2bfloat16(v[0] - __bfloat162float(h0));
                __nv_bfloat16 l1 = __float2bfloat16(v[1] - __bfloat162float(h1));
                __nv_bfloat16 l2 = __float2bfloat16(v[2] - __bfloat162float(h2));
                __nv_bfloat16 l3 = __float2bfloat16(v[3] - __bfloat162float(h3));
                *(__nv_bfloat162*)(outH + (size_t)rg * 2048 + cg)       = __nv_bfloat162(h0, h1);
                *(__nv_bfloat162*)(outL + (size_t)rg * 2048 + cg)       = __nv_bfloat162(l0, l1);
                *(__nv_bfloat162*)(outH + (size_t)(rg + 8) * 2048 + cg) = __nv_bfloat162(h2, h3);
                *(__nv_bfloat162*)(outL + (size_t)(rg + 8) * 2048 + cg) = __nv_bfloat162(l2, l3);
            }
        }
    }
}

// ---------------- fp32 -> (bf16 hi, bf16 lo) split ----------------
__global__ void split_hl(const float* __restrict__ src,
                         __nv_bfloat16* __restrict__ h, __nv_bfloat16* __restrict__ l)
{
    const size_t i = ((size_t)blockIdx.x * blockDim.x + threadIdx.x) * 4;
    float4 v = *(const float4*)(src + i);
    __nv_bfloat16 h0 = __float2bfloat16(v.x), h1 = __float2bfloat16(v.y);
    __nv_bfloat16 h2 = __float2bfloat16(v.z), h3 = __float2bfloat16(v.w);
    *(__nv_bfloat162*)(h + i)     = __nv_bfloat162(h0, h1);
    *(__nv_bfloat162*)(h + i + 2) = __nv_bfloat162(h2, h3);
    *(__nv_bfloat162*)(l + i)     = __nv_bfloat162(__float2bfloat16(v.x - __bfloat162float(h0)),
                                                   __float2bfloat16(v.y - __bfloat162float(h1)));
    *(__nv_bfloat162*)(l + i + 2) = __nv_bfloat162(__float2bfloat16(v.z - __bfloat162float(h2)),
                                                   __float2bfloat16(v.w - __bfloat162float(h3)));
}

// ---------------- column softmax (axis=1) ----------------
__global__ void col_stats(const float* __restrict__ S,
                          float* __restrict__ cmax, float* __restrict__ crsum)
{
    const int b = blockIdx.y;
    const int j = blockIdx.x * blockDim.x + threadIdx.x;
    const float* Sb = S + (size_t)b * NN * NN + j;
    float m[4] = {-1e30f, -1e30f, -1e30f, -1e30f};
    float s[4] = {0.f, 0.f, 0.f, 0.f};
    for (int i = 0; i < NN; i += 4) {
#pragma unroll
        for (int u = 0; u < 4; u++) {
            float v  = Sb[(size_t)(i + u) * NN];
            float nm = fmaxf(m[u], v);
            s[u] = s[u] * __expf(m[u] - nm) + __expf(v - nm);
            m[u] = nm;
        }
    }
    float M = fmaxf(fmaxf(m[0], m[1]), fmaxf(m[2], m[3]));
    float T = s[0] * __expf(m[0] - M) + s[1] * __expf(m[1] - M)
            + s[2] * __expf(m[2] - M) + s[3] * __expf(m[3] - M);
    cmax[b * NN + j]  = M;
    crsum[b * NN + j] = 1.0f / T;
}

__global__ void col_norm_split(const float* __restrict__ S,
                               const float* __restrict__ cmax, const float* __restrict__ crsum,
                               __nv_bfloat16* __restrict__ ah, __nv_bfloat16* __restrict__ al)
{
    const int b   = blockIdx.y;
    const int lin = blockIdx.x * blockDim.x + threadIdx.x;
    const int i   = lin >> 9;
    const int j4  = (lin & 511) << 2;
    const size_t off = (size_t)b * NN * NN + (size_t)i * NN + j4;

    float4 v  = *(const float4*)(S + off);
    float4 mx = *(const float4*)(cmax  + b * NN + j4);
    float4 rs = *(const float4*)(crsum + b * NN + j4);
    float a0 = __expf(v.x - mx.x) * rs.x;
    float a1 = __expf(v.y - mx.y) * rs.y;
    float a2 = __expf(v.z - mx.z) * rs.z;
    float a3 = __expf(v.w - mx.w) * rs.w;
    __nv_bfloat16 h0 = __float2bfloat16(a0), h1 = __float2bfloat16(a1);
    __nv_bfloat16 h2 = __float2bfloat16(a2), h3 = __float2bfloat16(a3);
    *(__nv_bfloat162*)(ah + off)     = __nv_bfloat162(h0, h1);
    *(__nv_bfloat162*)(ah + off + 2) = __nv_bfloat162(h2, h3);
    *(__nv_bfloat162*)(al + off)     = __nv_bfloat162(__float2bfloat16(a0 - __bfloat162float(h0)),
                                                      __float2bfloat16(a1 - __bfloat162float(h1)));
    *(__nv_bfloat162*)(al + off + 2) = __nv_bfloat162(__float2bfloat16(a2 - __bfloat162float(h2)),
                                                      __float2bfloat16(a3 - __bfloat162float(h3)));
}

// ---------------- launch ----------------
extern "C" void kernel_launch(void* const* d_in, const int* in_sizes, int n_in,
                              void* d_out, int out_size)
{
    const float* X = (const float*)d_in[0];
    const float* W = (const float*)d_in[1];
    // d_in[2] = bias: per-column constant on scores -> cancels in axis-1 softmax.
    // d_in[3] = gamma: scalar constant -> cancels likewise. Both unused.
    float* out = (float*)d_out;

    __nv_bfloat16 *xh, *xl, *wh, *wl, *qh, *ql, *ah, *al;
    float *s, *cmax, *csum;
    cudaGetSymbolAddress((void**)&xh, g_xh);  cudaGetSymbolAddress((void**)&xl, g_xl);
    cudaGetSymbolAddress((void**)&wh, g_wh);  cudaGetSymbolAddress((void**)&wl, g_wl);
    cudaGetSymbolAddress((void**)&qh, g_qh);  cudaGetSymbolAddress((void**)&ql, g_ql);
    cudaGetSymbolAddress((void**)&ah, g_ah);  cudaGetSymbolAddress((void**)&al, g_al);
    cudaGetSymbolAddress((void**)&s,  g_s);
    cudaGetSymbolAddress((void**)&cmax, g_cmax);
    cudaGetSymbolAddress((void**)&csum, g_csum);

    const int smem = STAGES * STAGE_BYTES;   // 192 KB
    cudaFuncSetAttribute(gemm_mma, cudaFuncAttributeMaxDynamicSharedMemorySize, smem);

    // split inputs into hi/lo bf16
    split_hl<<<(BATCH * NN * EE / 4) / 256, 256>>>(X, xh, xl);
    split_hl<<<(EE * EE / 4) / 256, 256>>>(W, wh, wl);

    const long long sXE = (long long)NN * EE;
    const long long sNN = (long long)NN * NN;

    // GEMM1: Q = X W^T  -> hi/lo bf16 (qh, ql).  (bias dropped: cancels)
    gemm_mma<<<dim3(EE / BN, (BATCH * NN) / BM, 1), 256, smem>>>(
        xh, xl, wh, wl, 0, 0, 0, nullptr, qh, ql, 1);

    // GEMM2: S[b] = Q[b] X[b]^T  (fp32)
    gemm_mma<<<dim3(NN / BN, NN / BM, BATCH), 256, smem>>>(
        qh, ql, xh, xl, sXE, sXE, sNN, s, nullptr, nullptr, 0);

    // softmax over axis=1 (columns), write split attn
    col_stats<<<dim3(NN / 256, BATCH), 256>>>(s, cmax, csum);
    col_norm_split<<<dim3((NN * NN / 4) / 256, BATCH), 256>>>(s, cmax, csum, ah, al);

    // GEMM3: out[b] = X[b] Attn[b]^T  (fp32)
    gemm_mma<<<dim3(NN / BN, NN / BM, BATCH), 256, smem>>>(
        xh, xl, ah, al, sXE, sNN, sNN, out, nullptr, nullptr, 0);
}